// round 13
// baseline (speedup 1.0000x reference)
#include <cuda_runtime.h>
#include <cuda_bf16.h>
#include <math.h>
#include <stdint.h>

// TopKRouter: logits = x @ W^T (16384x4096 @ 4096x64), softmax, top-2, renorm.
// Split-bf16 (hi/lo) 3-product mma.sync.m16n8k16 GEMM, K-split x4 across warps.
// Round 13: B stream via per-warp 2-stage cp.async ring (lookahead off the RF),
//           A register-pipelined; 96-reg cap -> 5 CTAs/SM (20 warps/SM).
// out fp32: [indices 16384*2][weights 16384*2][logits 16384*64]

#define TOKENS 16384
#define DIM    4096
#define NEXP   64
#define NKS    (DIM / 16)   // 256 k-steps total
#define KSW    (NKS / 4)    // 64 k-steps per warp

// smem: [bufB: 4 warps x 2 stages x 4KB = 32768][red: 3*32*33*4 = 12672]
#define SMEM_BYTES (32768 + 12672)

// Fragment-ordered pre-converted W, hi and lo interleaved:
// q = ((ks*8 + nt)*32 + lane): uint4 { hi(kb,kb+1), hi(kb+8,kb+9),
//                                      lo(kb,kb+1), lo(kb+8,kb+9) }
// with n = nt*8 + lane/4, kb = ks*16 + (lane%4)*2.
__device__ uint4 g_B[NKS * 8 * 32];

__device__ __forceinline__ uint32_t smem_u32(const void* p) {
    uint32_t a;
    asm("{ .reg .u64 t; cvta.to.shared.u64 t, %1; cvt.u32.u64 %0, t; }" : "=r"(a) : "l"(p));
    return a;
}

__device__ __forceinline__ void split2(float a, float b, unsigned& h, unsigned& l) {
    asm("cvt.rn.bf16x2.f32 %0, %1, %2;" : "=r"(h) : "f"(b), "f"(a));
    float ha = __uint_as_float(h << 16);
    float hb = __uint_as_float(h & 0xFFFF0000u);
    float ra = a - ha;
    float rb = b - hb;
    asm("cvt.rn.bf16x2.f32 %0, %1, %2;" : "=r"(l) : "f"(rb), "f"(ra));
}

__device__ __forceinline__ void mma16816(float* c, unsigned a0, unsigned a1,
                                         unsigned a2, unsigned a3,
                                         unsigned b0, unsigned b1) {
    asm volatile(
        "mma.sync.aligned.m16n8k16.row.col.f32.bf16.bf16.f32 "
        "{%0,%1,%2,%3}, {%4,%5,%6,%7}, {%8,%9}, {%0,%1,%2,%3};"
        : "+f"(c[0]), "+f"(c[1]), "+f"(c[2]), "+f"(c[3])
        : "r"(a0), "r"(a1), "r"(a2), "r"(a3), "r"(b0), "r"(b1));
}

__device__ __forceinline__ void cp16(uint32_t dst, const void* src) {
    asm volatile("cp.async.ca.shared.global [%0], [%1], 16;"
                 :: "r"(dst), "l"(src) : "memory");
}

// ---------------- W pre-convert (fragment order, interleaved) ----------------
__global__ void convert_w_kernel(const float* __restrict__ Wg) {
    int q = blockIdx.x * blockDim.x + threadIdx.x;   // 0..65535
    int ks   = q >> 8;
    int nt   = (q >> 5) & 7;
    int lane = q & 31;
    int n  = nt * 8 + (lane >> 2);
    int kb = ks * 16 + (lane & 3) * 2;
    const float* wr = Wg + (size_t)n * DIM + kb;
    unsigned hx, lx, hy, ly;
    split2(wr[0], wr[1], hx, lx);
    split2(wr[8], wr[9], hy, ly);
    g_B[q] = make_uint4(hx, hy, lx, ly);
}

__device__ __forceinline__ bool better(float v, int i, float v2, int i2) {
    return (v > v2) || (v == v2 && i < i2);
}

// ---------------- main kernel ----------------
// CTA: 4 warps, same 16 tokens, K quarters. Partial-acc reduce through smem.
__global__ __launch_bounds__(128, 5) void router_kernel(
    const float* __restrict__ x,
    float* __restrict__ out)
{
    extern __shared__ char sm[];
    float* red = (float*)(sm + 32768);

    const int tid  = threadIdx.x;
    const int wid  = tid >> 5;           // K quarter 0..3
    const int lane = tid & 31;
    const int r0   = blockIdx.x * 16 + (lane >> 2);   // rows r0, r0+8
    const int kbase = wid * KSW;

    const uint32_t smb   = smem_u32(sm);
    const uint32_t bBase = smb + wid * 8192;        // 2 stages x 4KB
    char* bReadBase = sm + wid * 8192;

    const float2* pA0 = (const float2*)(x + (size_t)r0 * DIM) + (lane & 3);
    const float2* pA1 = pA0 + 4 * DIM;   // row r0+8

    float acc[8][4];
    #pragma unroll
    for (int nt = 0; nt < 8; nt++)
        #pragma unroll
        for (int j = 0; j < 4; j++) acc[nt][j] = 0.0f;

    // ---- B issue helper: lane copies its own fragment for each nt ----
    auto issueB = [&](int s) {
        const int st = s & 1;
        const uint4* src = g_B + (size_t)(kbase + s) * 256 + lane;
        uint32_t dst = bBase + st * 4096 + lane * 16;
        #pragma unroll
        for (int nt = 0; nt < 8; nt++)
            cp16(dst + nt * 512, src + nt * 32);
    };

    issueB(0);
    asm volatile("cp.async.commit_group;" ::: "memory");
    issueB(1);
    asm volatile("cp.async.commit_group;" ::: "memory");

    // prime A register pipeline with step kbase
    float2 nA00 = __ldg(pA0 + kbase * 8);
    float2 nA01 = __ldg(pA0 + kbase * 8 + 4);
    float2 nA10 = __ldg(pA1 + kbase * 8);
    float2 nA11 = __ldg(pA1 + kbase * 8 + 4);

    #pragma unroll 2
    for (int s = 0; s < KSW; s++) {
        const int st = s & 1;

        // B(s) ready when <=1 group pending
        asm volatile("cp.async.wait_group 1;" ::: "memory");

        // pull B(s) into registers (own-lane addresses only -> no hazards when
        // this stage is overwritten by issueB(s+2) below)
        uint4 cB[8];
        const char* bp = bReadBase + st * 4096 + lane * 16;
        #pragma unroll
        for (int nt = 0; nt < 8; nt++)
            cB[nt] = *(const uint4*)(bp + nt * 512);

        // refill this stage for step s+2
        if (s + 2 < KSW) issueB(s + 2);
        asm volatile("cp.async.commit_group;" ::: "memory");

        // consume A(s), prefetch A(s+1) (wrap: redundant reload on last iter)
        float2 v00 = nA00, v01 = nA01, v10 = nA10, v11 = nA11;
        const int ks2 = kbase + ((s + 1) & (KSW - 1));
        nA00 = __ldg(pA0 + ks2 * 8);
        nA01 = __ldg(pA0 + ks2 * 8 + 4);
        nA10 = __ldg(pA1 + ks2 * 8);
        nA11 = __ldg(pA1 + ks2 * 8 + 4);

        unsigned ah0, ah1, ah2, ah3, al0, al1, al2, al3;
        split2(v00.x, v00.y, ah0, al0);
        split2(v10.x, v10.y, ah1, al1);
        split2(v01.x, v01.y, ah2, al2);
        split2(v11.x, v11.y, ah3, al3);

        #pragma unroll
        for (int nt = 0; nt < 8; nt++) {
            mma16816(acc[nt], ah0, ah1, ah2, ah3, cB[nt].x, cB[nt].y);   // hi*hi
            mma16816(acc[nt], ah0, ah1, ah2, ah3, cB[nt].z, cB[nt].w);   // hi*lo
            mma16816(acc[nt], al0, al1, al2, al3, cB[nt].x, cB[nt].y);   // lo*hi
        }
    }
    asm volatile("cp.async.wait_group 0;" ::: "memory");

    // ---- cross-warp K reduction via smem ----
    if (wid != 0) {
        float* dst = red + ((wid - 1) * 32 + lane) * 33;
        #pragma unroll
        for (int nt = 0; nt < 8; nt++)
            #pragma unroll
            for (int j = 0; j < 4; j++)
                dst[nt * 4 + j] = acc[nt][j];
    }
    __syncthreads();
    if (wid != 0) return;

    #pragma unroll
    for (int p = 0; p < 3; p++) {
        const float* src = red + (p * 32 + lane) * 33;
        #pragma unroll
        for (int nt = 0; nt < 8; nt++)
            #pragma unroll
            for (int j = 0; j < 4; j++)
                acc[nt][j] += src[nt * 4 + j];
    }

    // ---- write logits ----
    float* lg = out + 4 * TOKENS;
    const int cbase = (lane & 3) * 2;
    #pragma unroll
    for (int nt = 0; nt < 8; nt++) {
        int c = nt * 8 + cbase;
        *(float2*)(lg + (size_t)r0 * NEXP + c)       = make_float2(acc[nt][0], acc[nt][1]);
        *(float2*)(lg + (size_t)(r0 + 8) * NEXP + c) = make_float2(acc[nt][2], acc[nt][3]);
    }

    // ---- per-row top-2 (register scan + quad shuffle merge) ----
    #pragma unroll
    for (int half = 0; half < 2; half++) {
        const int row = r0 + half * 8;
        float m1 = -INFINITY, m2 = -INFINITY;
        int i1 = 0, i2 = 0;
        #pragma unroll
        for (int nt = 0; nt < 8; nt++) {
            #pragma unroll
            for (int j = 0; j < 2; j++) {
                float v = acc[nt][half * 2 + j];
                int e = nt * 8 + cbase + j;
                if (v > m1)      { m2 = m1; i2 = i1; m1 = v; i1 = e; }
                else if (v > m2) { m2 = v; i2 = e; }
            }
        }
        #pragma unroll
        for (int d = 1; d < 4; d <<= 1) {
            float om1 = __shfl_xor_sync(0xFFFFFFFF, m1, d);
            int   oi1 = __shfl_xor_sync(0xFFFFFFFF, i1, d);
            float om2 = __shfl_xor_sync(0xFFFFFFFF, m2, d);
            int   oi2 = __shfl_xor_sync(0xFFFFFFFF, i2, d);
            if (better(om1, oi1, m1, i1)) {
                float nm2; int ni2;
                if (better(m1, i1, om2, oi2)) { nm2 = m1; ni2 = i1; }
                else                          { nm2 = om2; ni2 = oi2; }
                m1 = om1; i1 = oi1; m2 = nm2; i2 = ni2;
            } else {
                if (better(om1, oi1, m2, i2)) { m2 = om1; i2 = oi1; }
            }
        }
        if ((lane & 3) == 0) {
            // top-2 renorm of full softmax == logistic of (m1 - m2); +1e-9 negligible
            float e2 = __expf(m2 - m1);
            float rcp = 1.0f / (1.0f + e2);
            out[(size_t)row * 2 + 0] = (float)i1;
            out[(size_t)row * 2 + 1] = (float)i2;
            out[2 * TOKENS + (size_t)row * 2 + 0] = rcp;
            out[2 * TOKENS + (size_t)row * 2 + 1] = e2 * rcp;
        }
    }
}

extern "C" void kernel_launch(void* const* d_in, const int* in_sizes, int n_in,
                              void* d_out, int out_size)
{
    const float* x  = (const float*)d_in[0];
    const float* Wg = (const float*)d_in[1];
    float* out = (float*)d_out;

    cudaFuncSetAttribute(router_kernel, cudaFuncAttributeMaxDynamicSharedMemorySize, SMEM_BYTES);

    convert_w_kernel<<<256, 256>>>(Wg);
    router_kernel<<<TOKENS / 16, 128, SMEM_BYTES>>>(x, out);
}

// round 14
// speedup vs baseline: 1.7069x; 1.7069x over previous
#include <cuda_runtime.h>
#include <cuda_bf16.h>
#include <math.h>
#include <stdint.h>

// TopKRouter: logits = x @ W^T (16384x4096 @ 4096x64), softmax, top-2, renorm.
// Split-bf16 (hi/lo) 3-product mma.sync.m16n8k16 GEMM.
// Round 14: R6 warp body unchanged; CTA = 8 warps x K/8 (256 thr) so the wave
//           structure is 3.5 rounds vs 3.46 ideal (R6 wasted ~13% on a 73%-full
//           second wave). Same 16 warps/SM, same 128-reg envelope.
// out fp32: [indices 16384*2][weights 16384*2][logits 16384*64]

#define TOKENS 16384
#define DIM    4096
#define NEXP   64
#define NKS    (DIM / 16)   // 256 k-steps total
#define KSW    (NKS / 8)    // 32 k-steps per warp

// Fragment-ordered pre-converted W, hi and lo interleaved:
// q = ((ks*8 + nt)*32 + lane): uint4 { hi(kb,kb+1), hi(kb+8,kb+9),
//                                      lo(kb,kb+1), lo(kb+8,kb+9) }
// with n = nt*8 + lane/4, kb = ks*16 + (lane%4)*2.
__device__ uint4 g_B[NKS * 8 * 32];

__device__ __forceinline__ void split2(float a, float b, unsigned& h, unsigned& l) {
    asm("cvt.rn.bf16x2.f32 %0, %1, %2;" : "=r"(h) : "f"(b), "f"(a));
    float ha = __uint_as_float(h << 16);
    float hb = __uint_as_float(h & 0xFFFF0000u);
    float ra = a - ha;
    float rb = b - hb;
    asm("cvt.rn.bf16x2.f32 %0, %1, %2;" : "=r"(l) : "f"(rb), "f"(ra));
}

__device__ __forceinline__ void mma16816(float* c, unsigned a0, unsigned a1,
                                         unsigned a2, unsigned a3,
                                         unsigned b0, unsigned b1) {
    asm volatile(
        "mma.sync.aligned.m16n8k16.row.col.f32.bf16.bf16.f32 "
        "{%0,%1,%2,%3}, {%4,%5,%6,%7}, {%8,%9}, {%0,%1,%2,%3};"
        : "+f"(c[0]), "+f"(c[1]), "+f"(c[2]), "+f"(c[3])
        : "r"(a0), "r"(a1), "r"(a2), "r"(a3), "r"(b0), "r"(b1));
}

// ---------------- W pre-convert (fragment order, interleaved) ----------------
__global__ void convert_w_kernel(const float* __restrict__ Wg) {
    int q = blockIdx.x * blockDim.x + threadIdx.x;   // 0..65535
    int ks   = q >> 8;
    int nt   = (q >> 5) & 7;
    int lane = q & 31;
    int n  = nt * 8 + (lane >> 2);
    int kb = ks * 16 + (lane & 3) * 2;
    const float* wr = Wg + (size_t)n * DIM + kb;
    unsigned hx, lx, hy, ly;
    split2(wr[0], wr[1], hx, lx);
    split2(wr[8], wr[9], hy, ly);
    g_B[q] = make_uint4(hx, hy, lx, ly);
}

__device__ __forceinline__ bool better(float v, int i, float v2, int i2) {
    return (v > v2) || (v == v2 && i < i2);
}

// ---------------- main kernel ----------------
// CTA: 8 warps, same 16 tokens, K eighths. Partial-acc reduce through smem.
__global__ __launch_bounds__(256, 2) void router_kernel(
    const float* __restrict__ x,
    float* __restrict__ out)
{
    __shared__ float red[7 * 32 * 33];   // 7 partials x 32 lanes x 32 floats, pad 33

    const int tid  = threadIdx.x;
    const int wid  = tid >> 5;           // K eighth 0..7
    const int lane = tid & 31;
    const int r0   = blockIdx.x * 16 + (lane >> 2);   // rows r0, r0+8
    const int kbase = wid * KSW;

    const float2* pA0 = (const float2*)(x + (size_t)r0 * DIM) + (lane & 3);
    const float2* pA1 = pA0 + 4 * DIM;   // row r0+8

    float acc[8][4];
    #pragma unroll
    for (int nt = 0; nt < 8; nt++)
        #pragma unroll
        for (int j = 0; j < 4; j++) acc[nt][j] = 0.0f;

    const uint4* __restrict__ B = g_B + lane;

    #pragma unroll 2
    for (int s = 0; s < KSW; s++) {
        const int ks = kbase + s;
        float2 v00 = __ldg(pA0 + ks * 8);
        float2 v01 = __ldg(pA0 + ks * 8 + 4);
        float2 v10 = __ldg(pA1 + ks * 8);
        float2 v11 = __ldg(pA1 + ks * 8 + 4);

        unsigned ah0, ah1, ah2, ah3, al0, al1, al2, al3;
        split2(v00.x, v00.y, ah0, al0);
        split2(v10.x, v10.y, ah1, al1);
        split2(v01.x, v01.y, ah2, al2);
        split2(v11.x, v11.y, ah3, al3);

        const uint4* b = B + ks * 256;
        #pragma unroll
        for (int nt = 0; nt < 8; nt++) {
            uint4 bv = __ldg(b + nt * 32);
            mma16816(acc[nt], ah0, ah1, ah2, ah3, bv.x, bv.y);   // hi * hi
            mma16816(acc[nt], ah0, ah1, ah2, ah3, bv.z, bv.w);   // hi * lo
            mma16816(acc[nt], al0, al1, al2, al3, bv.x, bv.y);   // lo * hi
        }
    }

    // ---- cross-warp K reduction via smem ----
    if (wid != 0) {
        float* dst = red + ((wid - 1) * 32 + lane) * 33;
        #pragma unroll
        for (int nt = 0; nt < 8; nt++)
            #pragma unroll
            for (int j = 0; j < 4; j++)
                dst[nt * 4 + j] = acc[nt][j];
    }
    __syncthreads();
    if (wid != 0) return;

    #pragma unroll
    for (int p = 0; p < 7; p++) {
        const float* src = red + (p * 32 + lane) * 33;
        #pragma unroll
        for (int nt = 0; nt < 8; nt++)
            #pragma unroll
            for (int j = 0; j < 4; j++)
                acc[nt][j] += src[nt * 4 + j];
    }

    // ---- write logits ----
    float* lg = out + 4 * TOKENS;
    const int cbase = (lane & 3) * 2;
    #pragma unroll
    for (int nt = 0; nt < 8; nt++) {
        int c = nt * 8 + cbase;
        *(float2*)(lg + (size_t)r0 * NEXP + c)       = make_float2(acc[nt][0], acc[nt][1]);
        *(float2*)(lg + (size_t)(r0 + 8) * NEXP + c) = make_float2(acc[nt][2], acc[nt][3]);
    }

    // ---- per-row top-2 (register scan + quad shuffle merge) ----
    #pragma unroll
    for (int half = 0; half < 2; half++) {
        const int row = r0 + half * 8;
        float m1 = -INFINITY, m2 = -INFINITY;
        int i1 = 0, i2 = 0;
        #pragma unroll
        for (int nt = 0; nt < 8; nt++) {
            #pragma unroll
            for (int j = 0; j < 2; j++) {
                float v = acc[nt][half * 2 + j];
                int e = nt * 8 + cbase + j;
                if (v > m1)      { m2 = m1; i2 = i1; m1 = v; i1 = e; }
                else if (v > m2) { m2 = v; i2 = e; }
            }
        }
        #pragma unroll
        for (int d = 1; d < 4; d <<= 1) {
            float om1 = __shfl_xor_sync(0xFFFFFFFF, m1, d);
            int   oi1 = __shfl_xor_sync(0xFFFFFFFF, i1, d);
            float om2 = __shfl_xor_sync(0xFFFFFFFF, m2, d);
            int   oi2 = __shfl_xor_sync(0xFFFFFFFF, i2, d);
            if (better(om1, oi1, m1, i1)) {
                float nm2; int ni2;
                if (better(m1, i1, om2, oi2)) { nm2 = m1; ni2 = i1; }
                else                          { nm2 = om2; ni2 = oi2; }
                m1 = om1; i1 = oi1; m2 = nm2; i2 = ni2;
            } else {
                if (better(om1, oi1, m2, i2)) { m2 = om1; i2 = oi1; }
            }
        }
        if ((lane & 3) == 0) {
            // top-2 renorm of full softmax == logistic of (m1 - m2); +1e-9 negligible
            float e2 = __expf(m2 - m1);
            float rcp = 1.0f / (1.0f + e2);
            out[(size_t)row * 2 + 0] = (float)i1;
            out[(size_t)row * 2 + 1] = (float)i2;
            out[2 * TOKENS + (size_t)row * 2 + 0] = rcp;
            out[2 * TOKENS + (size_t)row * 2 + 1] = e2 * rcp;
        }
    }
}

extern "C" void kernel_launch(void* const* d_in, const int* in_sizes, int n_in,
                              void* d_out, int out_size)
{
    const float* x  = (const float*)d_in[0];
    const float* Wg = (const float*)d_in[1];
    float* out = (float*)d_out;

    convert_w_kernel<<<256, 256>>>(Wg);
    router_kernel<<<TOKENS / 16, 256>>>(x, out);
}

// round 15
// speedup vs baseline: 1.9190x; 1.1243x over previous
#include <cuda_runtime.h>
#include <cuda_bf16.h>
#include <math.h>
#include <stdint.h>

// TopKRouter: logits = x @ W^T (16384x4096 @ 4096x64), softmax, top-2, renorm.
// Split-bf16 (hi/lo) 3-product mma.sync.m16n8k16 GEMM, K-split x4 across warps.
// Round 15: R6 config + k-permutation so A loads are float4/row (2 LDG.128 per
//           step instead of 4 LDG.64) — halves A's L1 line-touches. B's
//           pre-converted fragment layout applies the matching permutation.
// out fp32: [indices 16384*2][weights 16384*2][logits 16384*64]

#define TOKENS 16384
#define DIM    4096
#define NEXP   64
#define NKS    (DIM / 16)   // 256 k-steps total
#define KSW    (NKS / 4)    // 64 k-steps per warp

// Fragment-ordered pre-converted W, hi and lo interleaved, PERMUTED k:
// q = ((ks*8 + nt)*32 + lane), kb = ks*16 + (lane%4)*4, n = nt*8 + lane/4:
//   uint4 { hi(kb,kb+1), hi(kb+2,kb+3), lo(kb,kb+1), lo(kb+2,kb+3) }
// (slot pair "k" <- global kb..kb+1, slot pair "k+8" <- global kb+2..kb+3;
//  A applies the same permutation, so the dot product is unchanged.)
__device__ uint4 g_B[NKS * 8 * 32];

__device__ __forceinline__ void split2(float a, float b, unsigned& h, unsigned& l) {
    asm("cvt.rn.bf16x2.f32 %0, %1, %2;" : "=r"(h) : "f"(b), "f"(a));
    float ha = __uint_as_float(h << 16);
    float hb = __uint_as_float(h & 0xFFFF0000u);
    float ra = a - ha;
    float rb = b - hb;
    asm("cvt.rn.bf16x2.f32 %0, %1, %2;" : "=r"(l) : "f"(rb), "f"(ra));
}

__device__ __forceinline__ void mma16816(float* c, unsigned a0, unsigned a1,
                                         unsigned a2, unsigned a3,
                                         unsigned b0, unsigned b1) {
    asm volatile(
        "mma.sync.aligned.m16n8k16.row.col.f32.bf16.bf16.f32 "
        "{%0,%1,%2,%3}, {%4,%5,%6,%7}, {%8,%9}, {%0,%1,%2,%3};"
        : "+f"(c[0]), "+f"(c[1]), "+f"(c[2]), "+f"(c[3])
        : "r"(a0), "r"(a1), "r"(a2), "r"(a3), "r"(b0), "r"(b1));
}

// ---------------- W pre-convert (fragment order, permuted k) ----------------
__global__ void convert_w_kernel(const float* __restrict__ Wg) {
    int q = blockIdx.x * blockDim.x + threadIdx.x;   // 0..65535
    int ks   = q >> 8;
    int nt   = (q >> 5) & 7;
    int lane = q & 31;
    int n  = nt * 8 + (lane >> 2);
    int kb = ks * 16 + (lane & 3) * 4;
    const float* wr = Wg + (size_t)n * DIM + kb;
    unsigned hx, lx, hy, ly;
    split2(wr[0], wr[1], hx, lx);
    split2(wr[2], wr[3], hy, ly);
    g_B[q] = make_uint4(hx, hy, lx, ly);
}

__device__ __forceinline__ bool better(float v, int i, float v2, int i2) {
    return (v > v2) || (v == v2 && i < i2);
}

// ---------------- main kernel ----------------
// CTA: 4 warps, same 16 tokens, K quarters. Partial-acc reduce through smem.
__global__ __launch_bounds__(128, 4) void router_kernel(
    const float* __restrict__ x,
    float* __restrict__ out)
{
    __shared__ float red[3 * 32 * 33];   // 3 partials x 32 lanes x 32 floats, pad 33

    const int tid  = threadIdx.x;
    const int wid  = tid >> 5;           // K quarter 0..3
    const int lane = tid & 31;
    const int r0   = blockIdx.x * 16 + (lane >> 2);   // rows r0, r0+8
    const int kbase = wid * KSW;

    // A pointers: float4 granularity; quad index (lane&3) selects 16B within
    // each 64B k-step chunk of a row.
    const float4* pA0 = (const float4*)(x + (size_t)r0 * DIM) + (lane & 3);
    const float4* pA1 = pA0 + 2 * DIM;   // +8 rows = 8*DIM floats = 2*DIM float4

    float acc[8][4];
    #pragma unroll
    for (int nt = 0; nt < 8; nt++)
        #pragma unroll
        for (int j = 0; j < 4; j++) acc[nt][j] = 0.0f;

    const uint4* __restrict__ B = g_B + lane;

    #pragma unroll 2
    for (int s = 0; s < KSW; s++) {
        const int ks = kbase + s;
        float4 v0 = __ldg(pA0 + ks * 4);   // row r0:  global k = ks*16+(lane&3)*4 ..+3
        float4 v1 = __ldg(pA1 + ks * 4);   // row r0+8

        unsigned ah0, ah1, ah2, ah3, al0, al1, al2, al3;
        split2(v0.x, v0.y, ah0, al0);      // slot pair k      (row r0)
        split2(v1.x, v1.y, ah1, al1);      // slot pair k      (row r0+8)
        split2(v0.z, v0.w, ah2, al2);      // slot pair k+8    (row r0)
        split2(v1.z, v1.w, ah3, al3);      // slot pair k+8    (row r0+8)

        const uint4* b = B + ks * 256;
        #pragma unroll
        for (int nt = 0; nt < 8; nt++) {
            uint4 bv = __ldg(b + nt * 32);
            mma16816(acc[nt], ah0, ah1, ah2, ah3, bv.x, bv.y);   // hi * hi
            mma16816(acc[nt], ah0, ah1, ah2, ah3, bv.z, bv.w);   // hi * lo
            mma16816(acc[nt], al0, al1, al2, al3, bv.x, bv.y);   // lo * hi
        }
    }

    // ---- cross-warp K reduction via smem ----
    if (wid != 0) {
        float* dst = red + ((wid - 1) * 32 + lane) * 33;
        #pragma unroll
        for (int nt = 0; nt < 8; nt++)
            #pragma unroll
            for (int j = 0; j < 4; j++)
                dst[nt * 4 + j] = acc[nt][j];
    }
    __syncthreads();
    if (wid != 0) return;

    #pragma unroll
    for (int p = 0; p < 3; p++) {
        const float* src = red + (p * 32 + lane) * 33;
        #pragma unroll
        for (int nt = 0; nt < 8; nt++)
            #pragma unroll
            for (int j = 0; j < 4; j++)
                acc[nt][j] += src[nt * 4 + j];
    }

    // ---- write logits ----
    float* lg = out + 4 * TOKENS;
    const int cbase = (lane & 3) * 2;
    #pragma unroll
    for (int nt = 0; nt < 8; nt++) {
        int c = nt * 8 + cbase;
        *(float2*)(lg + (size_t)r0 * NEXP + c)       = make_float2(acc[nt][0], acc[nt][1]);
        *(float2*)(lg + (size_t)(r0 + 8) * NEXP + c) = make_float2(acc[nt][2], acc[nt][3]);
    }

    // ---- per-row top-2 (register scan + quad shuffle merge) ----
    #pragma unroll
    for (int half = 0; half < 2; half++) {
        const int row = r0 + half * 8;
        float m1 = -INFINITY, m2 = -INFINITY;
        int i1 = 0, i2 = 0;
        #pragma unroll
        for (int nt = 0; nt < 8; nt++) {
            #pragma unroll
            for (int j = 0; j < 2; j++) {
                float v = acc[nt][half * 2 + j];
                int e = nt * 8 + cbase + j;
                if (v > m1)      { m2 = m1; i2 = i1; m1 = v; i1 = e; }
                else if (v > m2) { m2 = v; i2 = e; }
            }
        }
        #pragma unroll
        for (int d = 1; d < 4; d <<= 1) {
            float om1 = __shfl_xor_sync(0xFFFFFFFF, m1, d);
            int   oi1 = __shfl_xor_sync(0xFFFFFFFF, i1, d);
            float om2 = __shfl_xor_sync(0xFFFFFFFF, m2, d);
            int   oi2 = __shfl_xor_sync(0xFFFFFFFF, i2, d);
            if (better(om1, oi1, m1, i1)) {
                float nm2; int ni2;
                if (better(m1, i1, om2, oi2)) { nm2 = m1; ni2 = i1; }
                else                          { nm2 = om2; ni2 = oi2; }
                m1 = om1; i1 = oi1; m2 = nm2; i2 = ni2;
            } else {
                if (better(om1, oi1, m2, i2)) { m2 = om1; i2 = oi1; }
            }
        }
        if ((lane & 3) == 0) {
            // top-2 renorm of full softmax == logistic of (m1 - m2); +1e-9 negligible
            float e2 = __expf(m2 - m1);
            float rcp = 1.0f / (1.0f + e2);
            out[(size_t)row * 2 + 0] = (float)i1;
            out[(size_t)row * 2 + 1] = (float)i2;
            out[2 * TOKENS + (size_t)row * 2 + 0] = rcp;
            out[2 * TOKENS + (size_t)row * 2 + 1] = e2 * rcp;
        }
    }
}

extern "C" void kernel_launch(void* const* d_in, const int* in_sizes, int n_in,
                              void* d_out, int out_size)
{
    const float* x  = (const float*)d_in[0];
    const float* Wg = (const float*)d_in[1];
    float* out = (float*)d_out;

    convert_w_kernel<<<256, 256>>>(Wg);
    router_kernel<<<TOKENS / 16, 128>>>(x, out);
}

// round 16
// speedup vs baseline: 1.9600x; 1.0213x over previous
#include <cuda_runtime.h>
#include <cuda_bf16.h>
#include <math.h>
#include <stdint.h>

// TopKRouter: logits = x @ W^T (16384x4096 @ 4096x64), softmax, top-2, renorm.
// Split-bf16 (hi/lo) 3-product mma.sync.m16n8k16 GEMM, K-split x4 across warps.
// Round 16: R15 + streaming cache policy ONLY (A loads .cs, logits stores .cs)
//           at the proven 128-reg / 4-CTA operating point. B keeps .ca so the
//           1MB weight stream stays L1/L2-resident against the 256MB x stream.
// out fp32: [indices 16384*2][weights 16384*2][logits 16384*64]

#define TOKENS 16384
#define DIM    4096
#define NEXP   64
#define NKS    (DIM / 16)   // 256 k-steps total
#define KSW    (NKS / 4)    // 64 k-steps per warp

// Fragment-ordered pre-converted W, hi and lo interleaved, PERMUTED k:
// q = ((ks*8 + nt)*32 + lane), kb = ks*16 + (lane%4)*4, n = nt*8 + lane/4:
//   uint4 { hi(kb,kb+1), hi(kb+2,kb+3), lo(kb,kb+1), lo(kb+2,kb+3) }
// A applies the same permutation (float4-contiguous per thread), so the
// dot product is unchanged.
__device__ uint4 g_B[NKS * 8 * 32];

__device__ __forceinline__ void split2(float a, float b, unsigned& h, unsigned& l) {
    asm("cvt.rn.bf16x2.f32 %0, %1, %2;" : "=r"(h) : "f"(b), "f"(a));
    float ha = __uint_as_float(h << 16);
    float hb = __uint_as_float(h & 0xFFFF0000u);
    float ra = a - ha;
    float rb = b - hb;
    asm("cvt.rn.bf16x2.f32 %0, %1, %2;" : "=r"(l) : "f"(rb), "f"(ra));
}

__device__ __forceinline__ void mma16816(float* c, unsigned a0, unsigned a1,
                                         unsigned a2, unsigned a3,
                                         unsigned b0, unsigned b1) {
    asm volatile(
        "mma.sync.aligned.m16n8k16.row.col.f32.bf16.bf16.f32 "
        "{%0,%1,%2,%3}, {%4,%5,%6,%7}, {%8,%9}, {%0,%1,%2,%3};"
        : "+f"(c[0]), "+f"(c[1]), "+f"(c[2]), "+f"(c[3])
        : "r"(a0), "r"(a1), "r"(a2), "r"(a3), "r"(b0), "r"(b1));
}

// ---------------- W pre-convert (fragment order, permuted k) ----------------
__global__ void convert_w_kernel(const float* __restrict__ Wg) {
    int q = blockIdx.x * blockDim.x + threadIdx.x;   // 0..65535
    int ks   = q >> 8;
    int nt   = (q >> 5) & 7;
    int lane = q & 31;
    int n  = nt * 8 + (lane >> 2);
    int kb = ks * 16 + (lane & 3) * 4;
    const float* wr = Wg + (size_t)n * DIM + kb;
    unsigned hx, lx, hy, ly;
    split2(wr[0], wr[1], hx, lx);
    split2(wr[2], wr[3], hy, ly);
    g_B[q] = make_uint4(hx, hy, lx, ly);
}

__device__ __forceinline__ bool better(float v, int i, float v2, int i2) {
    return (v > v2) || (v == v2 && i < i2);
}

// ---------------- main kernel ----------------
// CTA: 4 warps, same 16 tokens, K quarters. Partial-acc reduce through smem.
__global__ __launch_bounds__(128, 4) void router_kernel(
    const float* __restrict__ x,
    float* __restrict__ out)
{
    __shared__ float red[3 * 32 * 33];   // 3 partials x 32 lanes x 32 floats, pad 33

    const int tid  = threadIdx.x;
    const int wid  = tid >> 5;           // K quarter 0..3
    const int lane = tid & 31;
    const int r0   = blockIdx.x * 16 + (lane >> 2);   // rows r0, r0+8
    const int kbase = wid * KSW;

    // A pointers: float4 granularity; quad index (lane&3) selects 16B within
    // each 64B k-step chunk of a row.
    const float4* pA0 = (const float4*)(x + (size_t)r0 * DIM) + (lane & 3);
    const float4* pA1 = pA0 + 2 * DIM;   // +8 rows = 8*DIM floats = 2*DIM float4

    float acc[8][4];
    #pragma unroll
    for (int nt = 0; nt < 8; nt++)
        #pragma unroll
        for (int j = 0; j < 4; j++) acc[nt][j] = 0.0f;

    const uint4* __restrict__ B = g_B + lane;

    #pragma unroll 2
    for (int s = 0; s < KSW; s++) {
        const int ks = kbase + s;
        // x is strictly streaming (read once): evict-first so B stays resident
        float4 v0 = __ldcs(pA0 + ks * 4);   // row r0
        float4 v1 = __ldcs(pA1 + ks * 4);   // row r0+8

        unsigned ah0, ah1, ah2, ah3, al0, al1, al2, al3;
        split2(v0.x, v0.y, ah0, al0);      // slot pair k      (row r0)
        split2(v1.x, v1.y, ah1, al1);      // slot pair k      (row r0+8)
        split2(v0.z, v0.w, ah2, al2);      // slot pair k+8    (row r0)
        split2(v1.z, v1.w, ah3, al3);      // slot pair k+8    (row r0+8)

        const uint4* b = B + ks * 256;
        #pragma unroll
        for (int nt = 0; nt < 8; nt++) {
            uint4 bv = __ldg(b + nt * 32);
            mma16816(acc[nt], ah0, ah1, ah2, ah3, bv.x, bv.y);   // hi * hi
            mma16816(acc[nt], ah0, ah1, ah2, ah3, bv.z, bv.w);   // hi * lo
            mma16816(acc[nt], al0, al1, al2, al3, bv.x, bv.y);   // lo * hi
        }
    }

    // ---- cross-warp K reduction via smem ----
    if (wid != 0) {
        float* dst = red + ((wid - 1) * 32 + lane) * 33;
        #pragma unroll
        for (int nt = 0; nt < 8; nt++)
            #pragma unroll
            for (int j = 0; j < 4; j++)
                dst[nt * 4 + j] = acc[nt][j];
    }
    __syncthreads();
    if (wid != 0) return;

    #pragma unroll
    for (int p = 0; p < 3; p++) {
        const float* src = red + (p * 32 + lane) * 33;
        #pragma unroll
        for (int nt = 0; nt < 8; nt++)
            #pragma unroll
            for (int j = 0; j < 4; j++)
                acc[nt][j] += src[nt * 4 + j];
    }

    // ---- write logits (streaming stores: write-once data) ----
    float* lg = out + 4 * TOKENS;
    const int cbase = (lane & 3) * 2;
    #pragma unroll
    for (int nt = 0; nt < 8; nt++) {
        int c = nt * 8 + cbase;
        __stcs((float2*)(lg + (size_t)r0 * NEXP + c),       make_float2(acc[nt][0], acc[nt][1]));
        __stcs((float2*)(lg + (size_t)(r0 + 8) * NEXP + c), make_float2(acc[nt][2], acc[nt][3]));
    }

    // ---- per-row top-2 (register scan + quad shuffle merge) ----
    #pragma unroll
    for (int half = 0; half < 2; half++) {
        const int row = r0 + half * 8;
        float m1 = -INFINITY, m2 = -INFINITY;
        int i1 = 0, i2 = 0;
        #pragma unroll
        for (int nt = 0; nt < 8; nt++) {
            #pragma unroll
            for (int j = 0; j < 2; j++) {
                float v = acc[nt][half * 2 + j];
                int e = nt * 8 + cbase + j;
                if (v > m1)      { m2 = m1; i2 = i1; m1 = v; i1 = e; }
                else if (v > m2) { m2 = v; i2 = e; }
            }
        }
        #pragma unroll
        for (int d = 1; d < 4; d <<= 1) {
            float om1 = __shfl_xor_sync(0xFFFFFFFF, m1, d);
            int   oi1 = __shfl_xor_sync(0xFFFFFFFF, i1, d);
            float om2 = __shfl_xor_sync(0xFFFFFFFF, m2, d);
            int   oi2 = __shfl_xor_sync(0xFFFFFFFF, i2, d);
            if (better(om1, oi1, m1, i1)) {
                float nm2; int ni2;
                if (better(m1, i1, om2, oi2)) { nm2 = m1; ni2 = i1; }
                else                          { nm2 = om2; ni2 = oi2; }
                m1 = om1; i1 = oi1; m2 = nm2; i2 = ni2;
            } else {
                if (better(om1, oi1, m2, i2)) { m2 = om1; i2 = oi1; }
            }
        }
        if ((lane & 3) == 0) {
            // top-2 renorm of full softmax == logistic of (m1 - m2); +1e-9 negligible
            float e2 = __expf(m2 - m1);
            float rcp = 1.0f / (1.0f + e2);
            out[(size_t)row * 2 + 0] = (float)i1;
            out[(size_t)row * 2 + 1] = (float)i2;
            out[2 * TOKENS + (size_t)row * 2 + 0] = rcp;
            out[2 * TOKENS + (size_t)row * 2 + 1] = e2 * rcp;
        }
    }
}

extern "C" void kernel_launch(void* const* d_in, const int* in_sizes, int n_in,
                              void* d_out, int out_size)
{
    const float* x  = (const float*)d_in[0];
    const float* Wg = (const float*)d_in[1];
    float* out = (float*)d_out;

    convert_w_kernel<<<256, 256>>>(Wg);
    router_kernel<<<TOKENS / 16, 128>>>(x, out);
}

// round 17
// speedup vs baseline: 1.9965x; 1.0186x over previous
#include <cuda_runtime.h>
#include <cuda_bf16.h>
#include <math.h>
#include <stdint.h>

// TopKRouter: logits = x @ W^T (16384x4096 @ 4096x64), softmax, top-2, renorm.
// Split-bf16 (hi/lo) 3-product mma.sync.m16n8k16 GEMM, K-split x4 across warps.
// Round 17: R16 + wider compile-time schedule window (unroll 4) and per-step
//           batched B loads (explicit 8-deep LDG burst feeding the MMA block).
// out fp32: [indices 16384*2][weights 16384*2][logits 16384*64]

#define TOKENS 16384
#define DIM    4096
#define NEXP   64
#define NKS    (DIM / 16)   // 256 k-steps total
#define KSW    (NKS / 4)    // 64 k-steps per warp

// Fragment-ordered pre-converted W, hi and lo interleaved, PERMUTED k:
// q = ((ks*8 + nt)*32 + lane), kb = ks*16 + (lane%4)*4, n = nt*8 + lane/4:
//   uint4 { hi(kb,kb+1), hi(kb+2,kb+3), lo(kb,kb+1), lo(kb+2,kb+3) }
// A applies the same permutation (float4-contiguous per thread), so the
// dot product is unchanged.
__device__ uint4 g_B[NKS * 8 * 32];

__device__ __forceinline__ void split2(float a, float b, unsigned& h, unsigned& l) {
    asm("cvt.rn.bf16x2.f32 %0, %1, %2;" : "=r"(h) : "f"(b), "f"(a));
    float ha = __uint_as_float(h << 16);
    float hb = __uint_as_float(h & 0xFFFF0000u);
    float ra = a - ha;
    float rb = b - hb;
    asm("cvt.rn.bf16x2.f32 %0, %1, %2;" : "=r"(l) : "f"(rb), "f"(ra));
}

__device__ __forceinline__ void mma16816(float* c, unsigned a0, unsigned a1,
                                         unsigned a2, unsigned a3,
                                         unsigned b0, unsigned b1) {
    asm volatile(
        "mma.sync.aligned.m16n8k16.row.col.f32.bf16.bf16.f32 "
        "{%0,%1,%2,%3}, {%4,%5,%6,%7}, {%8,%9}, {%0,%1,%2,%3};"
        : "+f"(c[0]), "+f"(c[1]), "+f"(c[2]), "+f"(c[3])
        : "r"(a0), "r"(a1), "r"(a2), "r"(a3), "r"(b0), "r"(b1));
}

// ---------------- W pre-convert (fragment order, permuted k) ----------------
__global__ void convert_w_kernel(const float* __restrict__ Wg) {
    int q = blockIdx.x * blockDim.x + threadIdx.x;   // 0..65535
    int ks   = q >> 8;
    int nt   = (q >> 5) & 7;
    int lane = q & 31;
    int n  = nt * 8 + (lane >> 2);
    int kb = ks * 16 + (lane & 3) * 4;
    const float* wr = Wg + (size_t)n * DIM + kb;
    unsigned hx, lx, hy, ly;
    split2(wr[0], wr[1], hx, lx);
    split2(wr[2], wr[3], hy, ly);
    g_B[q] = make_uint4(hx, hy, lx, ly);
}

__device__ __forceinline__ bool better(float v, int i, float v2, int i2) {
    return (v > v2) || (v == v2 && i < i2);
}

// ---------------- main kernel ----------------
// CTA: 4 warps, same 16 tokens, K quarters. Partial-acc reduce through smem.
__global__ __launch_bounds__(128, 4) void router_kernel(
    const float* __restrict__ x,
    float* __restrict__ out)
{
    __shared__ float red[3 * 32 * 33];   // 3 partials x 32 lanes x 32 floats, pad 33

    const int tid  = threadIdx.x;
    const int wid  = tid >> 5;           // K quarter 0..3
    const int lane = tid & 31;
    const int r0   = blockIdx.x * 16 + (lane >> 2);   // rows r0, r0+8
    const int kbase = wid * KSW;

    // A pointers: float4 granularity; quad index (lane&3) selects 16B within
    // each 64B k-step chunk of a row.
    const float4* pA0 = (const float4*)(x + (size_t)r0 * DIM) + (lane & 3);
    const float4* pA1 = pA0 + 2 * DIM;   // +8 rows = 8*DIM floats = 2*DIM float4

    float acc[8][4];
    #pragma unroll
    for (int nt = 0; nt < 8; nt++)
        #pragma unroll
        for (int j = 0; j < 4; j++) acc[nt][j] = 0.0f;

    const uint4* __restrict__ B = g_B + lane;

    #pragma unroll 4
    for (int s = 0; s < KSW; s++) {
        const int ks = kbase + s;
        // x is strictly streaming (read once): evict-first so B stays resident
        float4 v0 = __ldcs(pA0 + ks * 4);   // row r0
        float4 v1 = __ldcs(pA1 + ks * 4);   // row r0+8

        // batched B burst: 8 independent LDG.128 up front
        const uint4* b = B + ks * 256;
        uint4 bv[8];
        #pragma unroll
        for (int nt = 0; nt < 8; nt++)
            bv[nt] = __ldg(b + nt * 32);

        unsigned ah0, ah1, ah2, ah3, al0, al1, al2, al3;
        split2(v0.x, v0.y, ah0, al0);      // slot pair k      (row r0)
        split2(v1.x, v1.y, ah1, al1);      // slot pair k      (row r0+8)
        split2(v0.z, v0.w, ah2, al2);      // slot pair k+8    (row r0)
        split2(v1.z, v1.w, ah3, al3);      // slot pair k+8    (row r0+8)

        #pragma unroll
        for (int nt = 0; nt < 8; nt++) {
            mma16816(acc[nt], ah0, ah1, ah2, ah3, bv[nt].x, bv[nt].y);   // hi * hi
            mma16816(acc[nt], ah0, ah1, ah2, ah3, bv[nt].z, bv[nt].w);   // hi * lo
            mma16816(acc[nt], al0, al1, al2, al3, bv[nt].x, bv[nt].y);   // lo * hi
        }
    }

    // ---- cross-warp K reduction via smem ----
    if (wid != 0) {
        float* dst = red + ((wid - 1) * 32 + lane) * 33;
        #pragma unroll
        for (int nt = 0; nt < 8; nt++)
            #pragma unroll
            for (int j = 0; j < 4; j++)
                dst[nt * 4 + j] = acc[nt][j];
    }
    __syncthreads();
    if (wid != 0) return;

    #pragma unroll
    for (int p = 0; p < 3; p++) {
        const float* src = red + (p * 32 + lane) * 33;
        #pragma unroll
        for (int nt = 0; nt < 8; nt++)
            #pragma unroll
            for (int j = 0; j < 4; j++)
                acc[nt][j] += src[nt * 4 + j];
    }

    // ---- write logits (streaming stores: write-once data) ----
    float* lg = out + 4 * TOKENS;
    const int cbase = (lane & 3) * 2;
    #pragma unroll
    for (int nt = 0; nt < 8; nt++) {
        int c = nt * 8 + cbase;
        __stcs((float2*)(lg + (size_t)r0 * NEXP + c),       make_float2(acc[nt][0], acc[nt][1]));
        __stcs((float2*)(lg + (size_t)(r0 + 8) * NEXP + c), make_float2(acc[nt][2], acc[nt][3]));
    }

    // ---- per-row top-2 (register scan + quad shuffle merge) ----
    #pragma unroll
    for (int half = 0; half < 2; half++) {
        const int row = r0 + half * 8;
        float m1 = -INFINITY, m2 = -INFINITY;
        int i1 = 0, i2 = 0;
        #pragma unroll
        for (int nt = 0; nt < 8; nt++) {
            #pragma unroll
            for (int j = 0; j < 2; j++) {
                float v = acc[nt][half * 2 + j];
                int e = nt * 8 + cbase + j;
                if (v > m1)      { m2 = m1; i2 = i1; m1 = v; i1 = e; }
                else if (v > m2) { m2 = v; i2 = e; }
            }
        }
        #pragma unroll
        for (int d = 1; d < 4; d <<= 1) {
            float om1 = __shfl_xor_sync(0xFFFFFFFF, m1, d);
            int   oi1 = __shfl_xor_sync(0xFFFFFFFF, i1, d);
            float om2 = __shfl_xor_sync(0xFFFFFFFF, m2, d);
            int   oi2 = __shfl_xor_sync(0xFFFFFFFF, i2, d);
            if (better(om1, oi1, m1, i1)) {
                float nm2; int ni2;
                if (better(m1, i1, om2, oi2)) { nm2 = m1; ni2 = i1; }
                else                          { nm2 = om2; ni2 = oi2; }
                m1 = om1; i1 = oi1; m2 = nm2; i2 = ni2;
            } else {
                if (better(om1, oi1, m2, i2)) { m2 = om1; i2 = oi1; }
            }
        }
        if ((lane & 3) == 0) {
            // top-2 renorm of full softmax == logistic of (m1 - m2); +1e-9 negligible
            float e2 = __expf(m2 - m1);
            float rcp = 1.0f / (1.0f + e2);
            out[(size_t)row * 2 + 0] = (float)i1;
            out[(size_t)row * 2 + 1] = (float)i2;
            out[2 * TOKENS + (size_t)row * 2 + 0] = rcp;
            out[2 * TOKENS + (size_t)row * 2 + 1] = e2 * rcp;
        }
    }
}

extern "C" void kernel_launch(void* const* d_in, const int* in_sizes, int n_in,
                              void* d_out, int out_size)
{
    const float* x  = (const float*)d_in[0];
    const float* Wg = (const float*)d_in[1];
    float* out = (float*)d_out;

    convert_w_kernel<<<256, 256>>>(Wg);
    router_kernel<<<TOKENS / 16, 128>>>(x, out);
}